// round 14
// baseline (speedup 1.0000x reference)
#include <cuda_runtime.h>
#include <cuda_fp16.h>

#define T_ 8
#define K_ 4
#define B_ 8
#define MAXP 262144
#define NCELL 31
#define NB (NCELL * NCELL * NCELL)   // 29791 bins
#define NBPAD 32768
#define PRE_BLOCKS 146               // 146*256 = 37376 = 512+4096+32768 voxels
#define NCOL (NCELL * NCELL)         // 961 z-columns
#define ZERO_BLOCKS 16               // 16*512 threads x int4 = 32768 ints per array
#define TILE_U4 5504                 // (512 fine + 576 mid + 288 coarse) slices * 4 uint4
#define MAXCHUNK 768                 // per-column 4-point chunk capacity (worst col ~360 pts)
#define SMEM_BYTES (TILE_U4 * 16 + MAXCHUNK * 8 + 16)

// Per-voxel time-expanded lattices in FP16:
// slice (voxel v, t) = uint2 = { half2(k0,k1), half2(k2,k3) } -> voxel line = 64 B
__device__ uint2 g_lat0h[512 * 8];
__device__ uint2 g_lat1h[4096 * 8];
__device__ uint2 g_lat2h[32768 * 8];
__device__ float g_basis[T_ * B_];

// Counting sort (padded to 32768 for vector scan; extras stay zero)
__device__ float4 g_sorted[MAXP];
__device__ __align__(16) int g_hist[NBPAD];   // zero-init at load; re-zeroed each call by main tail
__device__ __align__(16) int g_base[NBPAD];
__device__ __align__(16) int g_cur[NBPAD];

__constant__ float c_knots[12] = {0.f,0.f,0.f,0.f,1.f,2.f,4.f,8.f,16.f,16.f,16.f,16.f};

// ---------------------------------------------------------------------------
__device__ __forceinline__ int cell_of(float px, float py, float pz) {
    int fx = min(max((int)floorf(px), 0), NCELL - 1);
    int fy = min(max((int)floorf(py), 0), NCELL - 1);
    int fz = min(max((int)floorf(pz), 0), NCELL - 1);
    return (fx * NCELL + fy) * NCELL + fz;
}

// ---------------------------------------------------------------------------
// Launch 1: histogram + Cox-de Boor basis (block 0, threads 0-7)
// ---------------------------------------------------------------------------
__global__ void k1_hist_basis(const float* __restrict__ t_in,
                              const float* __restrict__ coords, int P) {
    int p = blockIdx.x * blockDim.x + threadIdx.x;
    if (p < P)
        atomicAdd(&g_hist[cell_of(coords[3*p], coords[3*p+1], coords[3*p+2])], 1);

    if (blockIdx.x == 0 && threadIdx.x < T_) {
        int ti = threadIdx.x;
        float t = t_in[ti];
        float N[11];
        #pragma unroll
        for (int i = 0; i < 11; i++) {
            float l = c_knots[i], r = c_knots[i + 1];
            bool m = (i < 10) ? (t >= l && t < r) : (t >= l && t <= r);
            N[i] = m ? 1.f : 0.f;
        }
        #pragma unroll
        for (int q = 1; q <= 3; q++) {
            float Nn[11];
            for (int i = 0; i < 11 - q; i++) {
                float l = c_knots[i], mid = c_knots[i + q];
                float rr = c_knots[i + 1], fr = c_knots[i + q + 1];
                float term = 0.f;
                if (mid > l)  term += (t - l) / (mid - l) * N[i];
                if (fr > rr)  term += (fr - t) / (fr - rr) * N[i + 1];
                Nn[i] = term;
            }
            for (int i = 0; i < 11 - q; i++) N[i] = Nn[i];
        }
        #pragma unroll
        for (int b = 0; b < B_; b++) g_basis[ti * B_ + b] = N[b];
    }
}

// ---------------------------------------------------------------------------
// Launch 2: vectorized exclusive scan of g_hist -> g_base (32768 entries)
// ---------------------------------------------------------------------------
__global__ void k2_scan() {
    __shared__ int wsum[32];
    int tid = threadIdx.x, lane = tid & 31, wid = tid >> 5;
    int4 v[8]; int s = 0;
    const int4* hp = reinterpret_cast<const int4*>(g_hist) + tid * 8;
    #pragma unroll
    for (int j = 0; j < 8; j++) { v[j] = hp[j]; s += v[j].x + v[j].y + v[j].z + v[j].w; }
    int incl = s;
    #pragma unroll
    for (int o = 1; o < 32; o <<= 1) { int t = __shfl_up_sync(~0u, incl, o); if (lane >= o) incl += t; }
    if (lane == 31) wsum[wid] = incl;
    __syncthreads();
    if (wid == 0) {
        int w = wsum[lane];
        int wi = w;
        #pragma unroll
        for (int o = 1; o < 32; o <<= 1) { int t = __shfl_up_sync(~0u, wi, o); if (lane >= o) wi += t; }
        wsum[lane] = wi - w;   // exclusive across warps
    }
    __syncthreads();
    int run = wsum[wid] + (incl - s);
    int4* bp = reinterpret_cast<int4*>(g_base) + tid * 8;
    #pragma unroll
    for (int j = 0; j < 8; j++) {
        int4 o;
        o.x = run; run += v[j].x;
        o.y = run; run += v[j].y;
        o.z = run; run += v[j].z;
        o.w = run; run += v[j].w;
        bp[j] = o;
    }
}

// ---------------------------------------------------------------------------
// Launch 3: fused scatter + lattice precompute
// ---------------------------------------------------------------------------
__device__ __forceinline__ unsigned h2u(__half2 h) { return *reinterpret_cast<unsigned*>(&h); }
__device__ __forceinline__ __half2 u2h(unsigned u) { __half2 h; *reinterpret_cast<unsigned*>(&h) = u; return h; }

__device__ __forceinline__ void pre_one(const float* __restrict__ stat,
                                        const float* __restrict__ coef,
                                        uint2* __restrict__ lat, int Nvox, int v) {
    float bas[T_ * B_];
    #pragma unroll
    for (int i = 0; i < T_ * B_; i++) bas[i] = g_basis[i];

    float st[K_];
    #pragma unroll
    for (int k = 0; k < K_; k++) st[k] = stat[k * Nvox + v];

    float cf[K_][B_];
    #pragma unroll
    for (int k = 0; k < K_; k++) {
        const float4* cp = reinterpret_cast<const float4*>(coef + ((size_t)(k * Nvox) + v) * B_);
        float4 c0 = cp[0], c1 = cp[1];
        cf[k][0] = c0.x; cf[k][1] = c0.y; cf[k][2] = c0.z; cf[k][3] = c0.w;
        cf[k][4] = c1.x; cf[k][5] = c1.y; cf[k][6] = c1.z; cf[k][7] = c1.w;
    }
    #pragma unroll
    for (int t = 0; t < T_; t++) {
        float o[K_];
        #pragma unroll
        for (int k = 0; k < K_; k++) {
            float s = st[k];
            #pragma unroll
            for (int b = 0; b < B_; b++) s = fmaf(bas[t * B_ + b], cf[k][b], s);
            o[k] = s;
        }
        uint2 r;
        r.x = h2u(__floats2half2_rn(o[0], o[1]));
        r.y = h2u(__floats2half2_rn(o[2], o[3]));
        lat[(size_t)v * 8 + t] = r;
    }
}

__global__ void k3_scatter_pre(const float* __restrict__ st0, const float* __restrict__ cf0,
                               const float* __restrict__ st1, const float* __restrict__ cf1,
                               const float* __restrict__ st2, const float* __restrict__ cf2,
                               const float* __restrict__ coords, int P) {
    if (blockIdx.x < PRE_BLOCKS) {
        int v = blockIdx.x * 256 + threadIdx.x;
        if (v < 512)       pre_one(st0, cf0, g_lat0h, 512,   v);
        else if (v < 4608) pre_one(st1, cf1, g_lat1h, 4096,  v - 512);
        else               pre_one(st2, cf2, g_lat2h, 32768, v - 4608);
    } else {
        int p = (blockIdx.x - PRE_BLOCKS) * 256 + threadIdx.x;
        if (p >= P) return;
        float px = coords[3*p], py = coords[3*p+1], pz = coords[3*p+2];
        int bin = cell_of(px, py, pz);
        int pos = g_base[bin] + atomicAdd(&g_cur[bin], 1);
        g_sorted[pos] = make_float4(px, py, pz, __int_as_float(p));
    }
}

// ---------------------------------------------------------------------------
// Launch 4 (PROFILED): per-column smem-tile tricubic gather with SAME-CELL
// chunk alignment. Block = one fine (fx,fy) z-column. A chunk = 4 points of
// ONE cell; warp = 2 chunks (one per half-warp). All 16 lanes of a half then
// read the SAME voxel slice per fine tap -> smem bank broadcast collapses the
// delivery phases (the R13 limiter).
// ---------------------------------------------------------------------------
__device__ __forceinline__ void cubw(float u, float w[4]) {
    float u2 = u * u, u3 = u2 * u;
    w[0] = (1.f / 6.f) * (1.f - 3.f * u + 3.f * u2 - u3);
    w[1] = (1.f / 6.f) * (4.f - 6.f * u2 + 3.f * u3);
    w[2] = (1.f / 6.f) * (1.f + 3.f * u + 3.f * u2 - 3.f * u3);
    w[3] = (1.f / 6.f) * u3;
}

__device__ __forceinline__ unsigned long long pack2(float w) {
    unsigned long long r;
    unsigned int wi = __float_as_uint(w);
    asm("mov.b64 %0, {%1, %1};" : "=l"(r) : "r"(wi));
    return r;
}

__device__ __forceinline__ unsigned long long pack2f(float a, float b) {
    unsigned long long r;
    asm("mov.b64 %0, {%1, %2};" : "=l"(r) : "f"(a), "f"(b));
    return r;
}

__device__ __forceinline__ void ffma2(unsigned long long& d,
                                      unsigned long long a,
                                      unsigned long long b) {
    asm("fma.rn.f32x2 %0, %1, %2, %0;" : "+l"(d) : "l"(a), "l"(b));
}

// one (a,b) row: 4 z-taps (half2 sums) folded into fp32x2 accumulators
__device__ __forceinline__ void row_accum(const uint4 h[4], const __half2 wzh[4],
                                          float wab, unsigned long long acc[4]) {
    const __half2 zero = __floats2half2_rn(0.f, 0.f);
    __half2 sA0 = zero, sA1 = zero, sB0 = zero, sB1 = zero;
    #pragma unroll
    for (int c = 0; c < 4; c++) {
        sA0 = __hfma2(u2h(h[c].x), wzh[c], sA0);
        sA1 = __hfma2(u2h(h[c].y), wzh[c], sA1);
        sB0 = __hfma2(u2h(h[c].z), wzh[c], sB0);
        sB1 = __hfma2(u2h(h[c].w), wzh[c], sB1);
    }
    unsigned long long wab2 = pack2(wab);
    float2 a0 = __half22float2(sA0);
    float2 a1 = __half22float2(sA1);
    float2 b0 = __half22float2(sB0);
    float2 b1 = __half22float2(sB1);
    ffma2(acc[0], pack2f(a0.x, a0.y), wab2);
    ffma2(acc[1], pack2f(a1.x, a1.y), wab2);
    ffma2(acc[2], pack2f(b0.x, b0.y), wab2);
    ffma2(acc[3], pack2f(b1.x, b1.y), wab2);
}

// XW = tile x/y width, NZ = tile z depth (= lattice z), TOFF = slice offset
template<int XW, int NZ, int TOFF>
__device__ __forceinline__ void accum_tile(const uint4* __restrict__ tile,
                                           int ox, int oy, int izm,
                                           const float wx[4], const float wy[4],
                                           const float wz[4],
                                           int tq, unsigned long long acc[4]) {
    __half2 wzh[4];
    int zq[4];
    #pragma unroll
    for (int c = 0; c < 4; c++) {
        wzh[c] = __floats2half2_rn(wz[c], wz[c]);
        zq[c] = min(max(izm + c, 0), NZ - 1) * 4 + tq;
    }
    #pragma unroll
    for (int a = 0; a < 4; a++) {
        #pragma unroll
        for (int b = 0; b < 4; b++) {
            const uint4* rp = tile + (TOFF + ((ox + a) * XW + (oy + b)) * NZ) * 4;
            uint4 h[4];
            #pragma unroll
            for (int c = 0; c < 4; c++) h[c] = rp[zq[c]];
            row_accum(h, wzh, wx[a] * wy[b], acc);
        }
    }
}

__global__ void __launch_bounds__(512, 2)
main_kernel(ulonglong2* __restrict__ out, int P) {
    if ((int)blockIdx.x >= NCOL) {
        // tail: restore hist/cur = 0 for the next graph replay
        int t = (blockIdx.x - NCOL) * 512 + threadIdx.x;   // 0..8191
        int4 z = make_int4(0, 0, 0, 0);
        reinterpret_cast<int4*>(g_hist)[t] = z;
        reinterpret_cast<int4*>(g_cur)[t] = z;
        return;
    }
    int col = blockIdx.x;
    int colBase = g_base[col * NCELL];
    int colEnd  = g_base[col * NCELL + NCELL];
    if (colEnd - colBase == 0) return;   // uniform early exit (before any sync)

    int fx = col / NCELL, fy = col % NCELL;
    int m0x = (fx * 15) / 31, m0y = (fy * 15) / 31;   // exact integer floors
    int c0x = (fx * 7) / 31,  c0y = (fy * 7) / 31;

    extern __shared__ uint4 tile[];
    int* tbStart = reinterpret_cast<int*>(tile + TILE_U4);
    int* tbEnd   = tbStart + MAXCHUNK;
    int* nchp    = tbEnd + MAXCHUNK;

    // ---- tile load (unchanged from R13) ----
    {
        const uint4* lf = reinterpret_cast<const uint4*>(g_lat2h);
        const uint4* lm = reinterpret_cast<const uint4*>(g_lat1h);
        const uint4* lc = reinterpret_cast<const uint4*>(g_lat0h);
        for (int i = threadIdx.x; i < TILE_U4; i += 512) {
            int s = i >> 2, part = i & 3;
            uint4 v;
            if (s < 512) {                       // fine 4x4x32
                int dz = s & 31, r = s >> 5;
                int dy = r & 3, dx = r >> 2;
                int X = min(max(fx - 1 + dx, 0), 31);
                int Y = min(max(fy - 1 + dy, 0), 31);
                v = lf[((X * 32 + Y) * 32 + dz) * 4 + part];
            } else if (s < 1088) {               // mid 6x6x16
                int s2 = s - 512;
                int dz = s2 & 15, r = s2 >> 4;
                int dx = r / 6, dy = r - dx * 6;
                int X = min(max(m0x - 1 + dx, 0), 15);
                int Y = min(max(m0y - 1 + dy, 0), 15);
                v = lm[((X * 16 + Y) * 16 + dz) * 4 + part];
            } else {                             // coarse 6x6x8
                int s3 = s - 1088;
                int dz = s3 & 7, r = s3 >> 3;
                int dx = r / 6, dy = r - dx * 6;
                int X = min(max(c0x - 1 + dx, 0), 7);
                int Y = min(max(c0y - 1 + dy, 0), 7);
                v = lc[((X * 8 + Y) * 8 + dz) * 4 + part];
            }
            tile[i] = v;
        }
    }

    // ---- chunk table: 4-point same-cell chunks (warp 0) ----
    if (threadIdx.x < 32) {
        int lane = threadIdx.x;
        int start = 0, end = 0, nch = 0;
        if (lane < NCELL) {
            start = g_base[col * NCELL + lane];
            end   = g_base[col * NCELL + lane + 1];
            nch = (end - start + 3) >> 2;
        }
        int incl = nch;
        #pragma unroll
        for (int o = 1; o < 32; o <<= 1) {
            int t = __shfl_up_sync(~0u, incl, o);
            if (lane >= o) incl += t;
        }
        int excl = incl - nch;
        int total = __shfl_sync(~0u, incl, 31);
        if (lane == 0) nchp[0] = min(total, MAXCHUNK);
        for (int k = 0; k < nch; k++) {
            int i = excl + k;
            if (i < MAXCHUNK) { tbStart[i] = start + k * 4; tbEnd[i] = end; }
        }
    }
    __syncthreads();
    int nch = nchp[0];

    int wid  = threadIdx.x >> 5;
    int lane = threadIdx.x & 31;
    int half = lane >> 4;        // chunk selector within warp (0/1)
    int sub  = (lane >> 2) & 3;  // point slot within chunk (0..3)
    int tq   = lane & 3;         // t-pair: owns t = 2tq, 2tq+1

    for (int pi = wid; pi * 2 < nch; pi += 16) {
        int ck = pi * 2 + half;
        bool haveChunk = ck < nch;
        int cs = tbStart[haveChunk ? ck : 0];
        int ce = haveChunk ? tbEnd[ck] : 0;
        int idx = cs + sub;
        bool active = haveChunk && (idx < ce);
        idx = haveChunk ? min(idx, ce - 1) : cs;
        float4 s = g_sorted[idx];

        unsigned long long acc[4] = {0ULL, 0ULL, 0ULL, 0ULL};

        // fine lattice (scale = 1): cell-local fractions
        {
            float ux = s.x - (float)fx;
            float uy = s.y - (float)fy;
            float fpz = floorf(s.z);
            int izm = (int)fpz - 1;
            float wx[4], wy[4], wz[4];
            cubw(ux, wx); cubw(uy, wy); cubw(s.z - fpz, wz);
            accum_tile<4, 32, 0>(tile, 0, 0, izm, wx, wy, wz, tq, acc);
        }
        // mid lattice
        {
            const float S = 15.f / 31.f;
            float cx = s.x * S, cy = s.y * S, cz = s.z * S;
            float flx = floorf(cx), fly = floorf(cy), flz = floorf(cz);
            int ox = min(max((int)flx - m0x, 0), 1);
            int oy = min(max((int)fly - m0y, 0), 1);
            int izm = (int)flz - 1;
            float wx[4], wy[4], wz[4];
            cubw(cx - flx, wx); cubw(cy - fly, wy); cubw(cz - flz, wz);
            accum_tile<6, 16, 512>(tile, ox, oy, izm, wx, wy, wz, tq, acc);
        }
        // coarse lattice
        {
            const float S = 7.f / 31.f;
            float cx = s.x * S, cy = s.y * S, cz = s.z * S;
            float flx = floorf(cx), fly = floorf(cy), flz = floorf(cz);
            int ox = min(max((int)flx - c0x, 0), 1);
            int oy = min(max((int)fly - c0y, 0), 1);
            int izm = (int)flz - 1;
            float wx[4], wy[4], wz[4];
            cubw(cx - flx, wx); cubw(cy - fly, wy); cubw(cz - flz, wz);
            accum_tile<6, 8, 1088>(tile, ox, oy, izm, wx, wy, wz, tq, acc);
        }

        if (active) {
            int orig = __float_as_int(s.w);
            ulonglong2 oA; oA.x = acc[0]; oA.y = acc[1];   // t = 2tq
            ulonglong2 oB; oB.x = acc[2]; oB.y = acc[3];   // t = 2tq+1
            out[(size_t)(2 * tq)     * P + orig] = oA;
            out[(size_t)(2 * tq + 1) * P + orig] = oB;
        }
    }
}

// ---------------------------------------------------------------------------
extern "C" void kernel_launch(void* const* d_in, const int* in_sizes, int n_in,
                              void* d_out, int out_size) {
    // metadata order: 0:t 1:coords 2:static_0 3:coeffs_0 4:static_1 5:coeffs_1
    //                 6:static_2 7:coeffs_2
    const float* t_in   = (const float*)d_in[0];
    const float* coords = (const float*)d_in[1];
    const float* st0 = (const float*)d_in[2];
    const float* cf0 = (const float*)d_in[3];
    const float* st1 = (const float*)d_in[4];
    const float* cf1 = (const float*)d_in[5];
    const float* st2 = (const float*)d_in[6];
    const float* cf2 = (const float*)d_in[7];
    int P = in_sizes[1] / 3;
    if (P > MAXP) P = MAXP;

    // opt-in for ~94KB dynamic smem (idempotent; legal during graph capture)
    cudaFuncSetAttribute(main_kernel, cudaFuncAttributeMaxDynamicSharedMemorySize, SMEM_BYTES);

    k1_hist_basis<<<(P + 255) / 256, 256>>>(t_in, coords, P);                       // 1
    k2_scan<<<1, 1024>>>();                                                         // 2
    k3_scatter_pre<<<PRE_BLOCKS + (P + 255) / 256, 256>>>(st0, cf0, st1, cf1,
                                                          st2, cf2, coords, P);     // 3
    main_kernel<<<NCOL + ZERO_BLOCKS, 512, SMEM_BYTES>>>((ulonglong2*)d_out, P);    // 4 (profiled)
}

// round 16
// speedup vs baseline: 1.1181x; 1.1181x over previous
#include <cuda_runtime.h>
#include <cuda_fp16.h>
#include <cstdint>

#define T_ 8
#define K_ 4
#define B_ 8
#define MAXP 262144
#define NCELL 31
#define NB (NCELL * NCELL * NCELL)   // 29791 bins
#define NBPAD 32768
#define PRE_BLOCKS 146               // 146*256 = 37376 = 512+4096+32768 voxels
#define NCOL (NCELL * NCELL)         // 961 z-columns
#define ZERO_BLOCKS 16               // 16*512 threads x int4 = 32768 ints per array
// scalar kernel tile: mid 6x6x16 (576 slices) + coarse 6x6x8 (288 slices)
#define TILE2_U4 3456                // 864 slices * 4 uint4
#define SMEM2_BYTES (TILE2_U4 * 16)  // 55296 B

// Per-voxel time-expanded lattices in FP16:
// slice (voxel v, t) = uint2 = { half2(k0,k1), half2(k2,k3) } -> voxel line = 64 B
__device__ uint2 g_lat0h[512 * 8];
__device__ uint2 g_lat1h[4096 * 8];
__device__ uint2 g_lat2h[32768 * 8];
__device__ float g_basis[T_ * B_];

// Counting sort (padded to 32768 for vector scan; extras stay zero)
__device__ float4 g_sorted[MAXP];
__device__ __align__(16) int g_hist[NBPAD];   // zero-init at load; re-zeroed each call by k5 tail
__device__ __align__(16) int g_base[NBPAD];
__device__ __align__(16) int g_cur[NBPAD];

// Fine-lattice GEMM staging: per sorted point, 32 f32 channels (n = t*4+k)
__device__ float g_fineC[MAXP * 32];

__constant__ float c_knots[12] = {0.f,0.f,0.f,0.f,1.f,2.f,4.f,8.f,16.f,16.f,16.f,16.f};

// ---------------------------------------------------------------------------
__device__ __forceinline__ int cell_of(float px, float py, float pz) {
    int fx = min(max((int)floorf(px), 0), NCELL - 1);
    int fy = min(max((int)floorf(py), 0), NCELL - 1);
    int fz = min(max((int)floorf(pz), 0), NCELL - 1);
    return (fx * NCELL + fy) * NCELL + fz;
}

__device__ __forceinline__ void cubw(float u, float w[4]) {
    float u2 = u * u, u3 = u2 * u;
    w[0] = (1.f / 6.f) * (1.f - 3.f * u + 3.f * u2 - u3);
    w[1] = (1.f / 6.f) * (4.f - 6.f * u2 + 3.f * u3);
    w[2] = (1.f / 6.f) * (1.f + 3.f * u + 3.f * u2 - 3.f * u3);
    w[3] = (1.f / 6.f) * u3;
}

// ---------------------------------------------------------------------------
// Launch 1: histogram + Cox-de Boor basis (block 0, threads 0-7)
// ---------------------------------------------------------------------------
__global__ void k1_hist_basis(const float* __restrict__ t_in,
                              const float* __restrict__ coords, int P) {
    int p = blockIdx.x * blockDim.x + threadIdx.x;
    if (p < P)
        atomicAdd(&g_hist[cell_of(coords[3*p], coords[3*p+1], coords[3*p+2])], 1);

    if (blockIdx.x == 0 && threadIdx.x < T_) {
        int ti = threadIdx.x;
        float t = t_in[ti];
        float N[11];
        #pragma unroll
        for (int i = 0; i < 11; i++) {
            float l = c_knots[i], r = c_knots[i + 1];
            bool m = (i < 10) ? (t >= l && t < r) : (t >= l && t <= r);
            N[i] = m ? 1.f : 0.f;
        }
        #pragma unroll
        for (int q = 1; q <= 3; q++) {
            float Nn[11];
            for (int i = 0; i < 11 - q; i++) {
                float l = c_knots[i], mid = c_knots[i + q];
                float rr = c_knots[i + 1], fr = c_knots[i + q + 1];
                float term = 0.f;
                if (mid > l)  term += (t - l) / (mid - l) * N[i];
                if (fr > rr)  term += (fr - t) / (fr - rr) * N[i + 1];
                Nn[i] = term;
            }
            for (int i = 0; i < 11 - q; i++) N[i] = Nn[i];
        }
        #pragma unroll
        for (int b = 0; b < B_; b++) g_basis[ti * B_ + b] = N[b];
    }
}

// ---------------------------------------------------------------------------
// Launch 2: vectorized exclusive scan of g_hist -> g_base (32768 entries)
// ---------------------------------------------------------------------------
__global__ void k2_scan() {
    __shared__ int wsum[32];
    int tid = threadIdx.x, lane = tid & 31, wid = tid >> 5;
    int4 v[8]; int s = 0;
    const int4* hp = reinterpret_cast<const int4*>(g_hist) + tid * 8;
    #pragma unroll
    for (int j = 0; j < 8; j++) { v[j] = hp[j]; s += v[j].x + v[j].y + v[j].z + v[j].w; }
    int incl = s;
    #pragma unroll
    for (int o = 1; o < 32; o <<= 1) { int t = __shfl_up_sync(~0u, incl, o); if (lane >= o) incl += t; }
    if (lane == 31) wsum[wid] = incl;
    __syncthreads();
    if (wid == 0) {
        int w = wsum[lane];
        int wi = w;
        #pragma unroll
        for (int o = 1; o < 32; o <<= 1) { int t = __shfl_up_sync(~0u, wi, o); if (lane >= o) wi += t; }
        wsum[lane] = wi - w;   // exclusive across warps
    }
    __syncthreads();
    int run = wsum[wid] + (incl - s);
    int4* bp = reinterpret_cast<int4*>(g_base) + tid * 8;
    #pragma unroll
    for (int j = 0; j < 8; j++) {
        int4 o;
        o.x = run; run += v[j].x;
        o.y = run; run += v[j].y;
        o.z = run; run += v[j].z;
        o.w = run; run += v[j].w;
        bp[j] = o;
    }
}

// ---------------------------------------------------------------------------
// Launch 3: fused scatter + lattice precompute
// ---------------------------------------------------------------------------
__device__ __forceinline__ unsigned h2u(__half2 h) { return *reinterpret_cast<unsigned*>(&h); }
__device__ __forceinline__ __half2 u2h(unsigned u) { __half2 h; *reinterpret_cast<unsigned*>(&h) = u; return h; }

__device__ __forceinline__ void pre_one(const float* __restrict__ stat,
                                        const float* __restrict__ coef,
                                        uint2* __restrict__ lat, int Nvox, int v) {
    float bas[T_ * B_];
    #pragma unroll
    for (int i = 0; i < T_ * B_; i++) bas[i] = g_basis[i];

    float st[K_];
    #pragma unroll
    for (int k = 0; k < K_; k++) st[k] = stat[k * Nvox + v];

    float cf[K_][B_];
    #pragma unroll
    for (int k = 0; k < K_; k++) {
        const float4* cp = reinterpret_cast<const float4*>(coef + ((size_t)(k * Nvox) + v) * B_);
        float4 c0 = cp[0], c1 = cp[1];
        cf[k][0] = c0.x; cf[k][1] = c0.y; cf[k][2] = c0.z; cf[k][3] = c0.w;
        cf[k][4] = c1.x; cf[k][5] = c1.y; cf[k][6] = c1.z; cf[k][7] = c1.w;
    }
    #pragma unroll
    for (int t = 0; t < T_; t++) {
        float o[K_];
        #pragma unroll
        for (int k = 0; k < K_; k++) {
            float s = st[k];
            #pragma unroll
            for (int b = 0; b < B_; b++) s = fmaf(bas[t * B_ + b], cf[k][b], s);
            o[k] = s;
        }
        uint2 r;
        r.x = h2u(__floats2half2_rn(o[0], o[1]));
        r.y = h2u(__floats2half2_rn(o[2], o[3]));
        lat[(size_t)v * 8 + t] = r;
    }
}

__global__ void k3_scatter_pre(const float* __restrict__ st0, const float* __restrict__ cf0,
                               const float* __restrict__ st1, const float* __restrict__ cf1,
                               const float* __restrict__ st2, const float* __restrict__ cf2,
                               const float* __restrict__ coords, int P) {
    if (blockIdx.x < PRE_BLOCKS) {
        int v = blockIdx.x * 256 + threadIdx.x;
        if (v < 512)       pre_one(st0, cf0, g_lat0h, 512,   v);
        else if (v < 4608) pre_one(st1, cf1, g_lat1h, 4096,  v - 512);
        else               pre_one(st2, cf2, g_lat2h, 32768, v - 4608);
    } else {
        int p = (blockIdx.x - PRE_BLOCKS) * 256 + threadIdx.x;
        if (p >= P) return;
        float px = coords[3*p], py = coords[3*p+1], pz = coords[3*p+2];
        int bin = cell_of(px, py, pz);
        int pos = g_base[bin] + atomicAdd(&g_cur[bin], 1);
        g_sorted[pos] = make_float4(px, py, pz, __int_as_float(p));
    }
}

// ---------------------------------------------------------------------------
// Launch 4: fine-lattice per-cell GEMM (HMMA m16n8k16, f16 in / f32 out).
// Block = column (fx,fy). Warp = cell; per cell-chunk of <=16 points:
//   A [16 pts x 64 taps] (weights, built in registers per A-fragment layout)
//   B [64 taps x 32 ch]  (fine tile slices via ldmatrix.x2.trans, loaded
//                         once per cell instead of once per point)
//   C staged to g_fineC[pt][32] f32 (n = t*4+k).
// ---------------------------------------------------------------------------
__device__ __forceinline__ unsigned packh2(float a, float b) {
    __half2 h = __floats2half2_rn(a, b);
    return *reinterpret_cast<unsigned*>(&h);
}

__global__ void __launch_bounds__(256) k4_fine_gemm(int P) {
    int col = blockIdx.x;                 // 0..960
    int fx = col / NCELL, fy = col % NCELL;
    int colBase = g_base[col * NCELL];
    int colEnd  = g_base[col * NCELL + NCELL];
    if (colBase == colEnd) return;

    __shared__ uint4 ftile[2048];              // fine 4x4x32 window, 32KB
    __shared__ __half wsm[8][16][12];          // per warp: wx[4],wy[4],wz[4] per point

    const uint4* lf = reinterpret_cast<const uint4*>(g_lat2h);
    for (int i = threadIdx.x; i < 2048; i += 256) {
        int s = i >> 2, part = i & 3;
        int z = s & 31, r = s >> 5;
        int dy = r & 3, dx = r >> 2;
        int X = min(max(fx - 1 + dx, 0), 31);
        int Y = min(max(fy - 1 + dy, 0), 31);
        ftile[i] = lf[((X * 32 + Y) * 32 + z) * 4 + part];
    }
    __syncthreads();

    int wid = threadIdx.x >> 5, lane = threadIdx.x & 31;
    unsigned tileS = (unsigned)__cvta_generic_to_shared(ftile);

    int g  = lane >> 2;               // A rows g, g+8
    int q  = lane & 3;
    int b0 = q >> 1;                  // b cols: b0, b0+2
    int c0 = (q & 1) * 2;             // c cols: c0, c0+1
    int j  = lane & 15;               // B fragment row for ldmatrix
    int bb = j >> 2, cc = j & 3;

    for (int ci = wid; ci < NCELL; ci += 8) {
        int cs = g_base[col * NCELL + ci];
        int ce = g_base[col * NCELL + ci + 1];
        if (cs >= ce) continue;
        int izm = ci - 1;
        int zc = min(max(izm + cc, 0), 31);
        // B row base address for this lane: slice ((a*4+bb)*32 + zc), a added per kchunk
        unsigned rowBase = tileS + (((bb * 32) + zc) << 6);

        for (int st = cs; st < ce; st += 16) {
            if (lane < 16) {
                int idx = min(st + lane, ce - 1);
                float4 s = g_sorted[idx];
                float wx[4], wy[4], wz[4];
                cubw(s.x - (float)fx, wx);
                cubw(s.y - (float)fy, wy);
                cubw(s.z - floorf(s.z), wz);
                #pragma unroll
                for (int k = 0; k < 4; k++) {
                    wsm[wid][lane][k]     = __float2half(wx[k]);
                    wsm[wid][lane][4 + k] = __float2half(wy[k]);
                    wsm[wid][lane][8 + k] = __float2half(wz[k]);
                }
            }
            __syncwarp();

            // per-lane wy*wz products for its 2 points (f32)
            float wyz[2][2][2];
            #pragma unroll
            for (int pi = 0; pi < 2; pi++) {
                int pt = g + 8 * pi;
                float wyA = __half2float(wsm[wid][pt][4 + b0]);
                float wyB = __half2float(wsm[wid][pt][4 + b0 + 2]);
                float wzA = __half2float(wsm[wid][pt][8 + c0]);
                float wzB = __half2float(wsm[wid][pt][8 + c0 + 1]);
                wyz[pi][0][0] = wyA * wzA; wyz[pi][0][1] = wyA * wzB;
                wyz[pi][1][0] = wyB * wzA; wyz[pi][1][1] = wyB * wzB;
            }

            float c[4][4];
            #pragma unroll
            for (int nc = 0; nc < 4; nc++)
                #pragma unroll
                for (int e = 0; e < 4; e++) c[nc][e] = 0.f;

            #pragma unroll
            for (int a = 0; a < 4; a++) {
                float wxg = __half2float(wsm[wid][g][a]);
                float wxh = __half2float(wsm[wid][g + 8][a]);
                unsigned a0 = packh2(wxg * wyz[0][0][0], wxg * wyz[0][0][1]);
                unsigned a1 = packh2(wxh * wyz[1][0][0], wxh * wyz[1][0][1]);
                unsigned a2 = packh2(wxg * wyz[0][1][0], wxg * wyz[0][1][1]);
                unsigned a3 = packh2(wxh * wyz[1][1][0], wxh * wyz[1][1][1]);
                unsigned rAddr = rowBase + a * 8192;   // a*4 slices * 32 z * 64B
                #pragma unroll
                for (int nc = 0; nc < 4; nc++) {
                    unsigned br0, br1;
                    asm volatile(
                        "ldmatrix.sync.aligned.m8n8.x2.trans.shared.b16 {%0,%1}, [%2];"
                        : "=r"(br0), "=r"(br1) : "r"(rAddr + nc * 16));
                    asm volatile(
                        "mma.sync.aligned.m16n8k16.row.col.f32.f16.f16.f32 "
                        "{%0,%1,%2,%3}, {%4,%5,%6,%7}, {%8,%9}, {%0,%1,%2,%3};"
                        : "+f"(c[nc][0]), "+f"(c[nc][1]), "+f"(c[nc][2]), "+f"(c[nc][3])
                        : "r"(a0), "r"(a1), "r"(a2), "r"(a3), "r"(br0), "r"(br1));
                }
            }

            // writeback: C row g -> point st+g, row g+8 -> st+g+8
            int n0 = 2 * q;
            int pA = st + g, pB = st + g + 8;
            #pragma unroll
            for (int nc = 0; nc < 4; nc++) {
                if (pA < ce) {
                    float2 v; v.x = c[nc][0]; v.y = c[nc][1];
                    *reinterpret_cast<float2*>(&g_fineC[(size_t)pA * 32 + nc * 8 + n0]) = v;
                }
                if (pB < ce) {
                    float2 v; v.x = c[nc][2]; v.y = c[nc][3];
                    *reinterpret_cast<float2*>(&g_fineC[(size_t)pB * 32 + nc * 8 + n0]) = v;
                }
            }
            __syncwarp();
        }
    }
}

// ---------------------------------------------------------------------------
// Launch 5: scalar mid+coarse gather (R13 structure, fine removed), acc
// initialized from g_fineC. Tail blocks re-zero hist/cur for next replay.
// ---------------------------------------------------------------------------
__device__ __forceinline__ unsigned long long pack2(float w) {
    unsigned long long r;
    unsigned int wi = __float_as_uint(w);
    asm("mov.b64 %0, {%1, %1};" : "=l"(r) : "r"(wi));
    return r;
}

__device__ __forceinline__ unsigned long long pack2f(float a, float b) {
    unsigned long long r;
    asm("mov.b64 %0, {%1, %2};" : "=l"(r) : "f"(a), "f"(b));
    return r;
}

__device__ __forceinline__ void ffma2(unsigned long long& d,
                                      unsigned long long a,
                                      unsigned long long b) {
    asm("fma.rn.f32x2 %0, %1, %2, %0;" : "+l"(d) : "l"(a), "l"(b));
}

__device__ __forceinline__ void row_accum(const uint4 h[4], const __half2 wzh[4],
                                          float wab, unsigned long long acc[4]) {
    const __half2 zero = __floats2half2_rn(0.f, 0.f);
    __half2 sA0 = zero, sA1 = zero, sB0 = zero, sB1 = zero;
    #pragma unroll
    for (int c = 0; c < 4; c++) {
        sA0 = __hfma2(u2h(h[c].x), wzh[c], sA0);
        sA1 = __hfma2(u2h(h[c].y), wzh[c], sA1);
        sB0 = __hfma2(u2h(h[c].z), wzh[c], sB0);
        sB1 = __hfma2(u2h(h[c].w), wzh[c], sB1);
    }
    unsigned long long wab2 = pack2(wab);
    float2 a0 = __half22float2(sA0);
    float2 a1 = __half22float2(sA1);
    float2 b0 = __half22float2(sB0);
    float2 b1 = __half22float2(sB1);
    ffma2(acc[0], pack2f(a0.x, a0.y), wab2);
    ffma2(acc[1], pack2f(a1.x, a1.y), wab2);
    ffma2(acc[2], pack2f(b0.x, b0.y), wab2);
    ffma2(acc[3], pack2f(b1.x, b1.y), wab2);
}

template<int XW, int NZ, int TOFF>
__device__ __forceinline__ void accum_tile(const uint4* __restrict__ tile,
                                           int ox, int oy, int izm,
                                           const float wx[4], const float wy[4],
                                           const float wz[4],
                                           int tq, unsigned long long acc[4]) {
    __half2 wzh[4];
    int zq[4];
    #pragma unroll
    for (int c = 0; c < 4; c++) {
        wzh[c] = __floats2half2_rn(wz[c], wz[c]);
        zq[c] = min(max(izm + c, 0), NZ - 1) * 4 + tq;
    }
    #pragma unroll
    for (int a = 0; a < 4; a++) {
        #pragma unroll
        for (int b = 0; b < 4; b++) {
            const uint4* rp = tile + (TOFF + ((ox + a) * XW + (oy + b)) * NZ) * 4;
            uint4 h[4];
            #pragma unroll
            for (int c = 0; c < 4; c++) h[c] = rp[zq[c]];
            row_accum(h, wzh, wx[a] * wy[b], acc);
        }
    }
}

__global__ void __launch_bounds__(512, 2)
k5_main(ulonglong2* __restrict__ out, int P) {
    if ((int)blockIdx.x >= NCOL) {
        int t = (blockIdx.x - NCOL) * 512 + threadIdx.x;   // 0..8191
        int4 z = make_int4(0, 0, 0, 0);
        reinterpret_cast<int4*>(g_hist)[t] = z;
        reinterpret_cast<int4*>(g_cur)[t] = z;
        return;
    }
    int col = blockIdx.x;
    int colBase = g_base[col * NCELL];
    int colEnd  = g_base[col * NCELL + NCELL];
    int count = colEnd - colBase;
    if (count == 0) return;

    int fx = col / NCELL, fy = col % NCELL;
    int m0x = (fx * 15) / 31, m0y = (fy * 15) / 31;
    int c0x = (fx * 7) / 31,  c0y = (fy * 7) / 31;

    extern __shared__ uint4 tile[];   // mid 576 slices | coarse 288 slices
    {
        const uint4* lm = reinterpret_cast<const uint4*>(g_lat1h);
        const uint4* lc = reinterpret_cast<const uint4*>(g_lat0h);
        for (int i = threadIdx.x; i < TILE2_U4; i += 512) {
            int s = i >> 2, part = i & 3;
            uint4 v;
            if (s < 576) {                       // mid 6x6x16
                int dz = s & 15, r = s >> 4;
                int dx = r / 6, dy = r - dx * 6;
                int X = min(max(m0x - 1 + dx, 0), 15);
                int Y = min(max(m0y - 1 + dy, 0), 15);
                v = lm[((X * 16 + Y) * 16 + dz) * 4 + part];
            } else {                             // coarse 6x6x8
                int s3 = s - 576;
                int dz = s3 & 7, r = s3 >> 3;
                int dx = r / 6, dy = r - dx * 6;
                int X = min(max(c0x - 1 + dx, 0), 7);
                int Y = min(max(c0y - 1 + dy, 0), 7);
                v = lc[((X * 8 + Y) * 8 + dz) * 4 + part];
            }
            tile[i] = v;
        }
    }
    __syncthreads();

    int wid  = threadIdx.x >> 5;
    int lane = threadIdx.x & 31;
    int sub  = lane >> 2;     // point slot within warp (0..7)
    int tq   = lane & 3;      // t-pair: owns t = 2tq, 2tq+1
    int rounds = (count + 127) >> 7;    // 16 warps x 8 points per round

    for (int r = 0; r < rounds; r++) {
        int chunk = colBase + ((r * 16 + wid) << 3);
        if (chunk >= colEnd) continue;
        int idx = chunk + sub;
        bool active = idx < colEnd;
        idx = min(idx, colEnd - 1);
        float4 s = g_sorted[idx];

        // init accumulators from fine-GEMM staging (n = t*4+k, f32)
        unsigned long long acc[4];
        {
            const float4* cp = reinterpret_cast<const float4*>(&g_fineC[(size_t)idx * 32 + 8 * tq]);
            float4 f0 = cp[0], f1 = cp[1];
            acc[0] = pack2f(f0.x, f0.y);
            acc[1] = pack2f(f0.z, f0.w);
            acc[2] = pack2f(f1.x, f1.y);
            acc[3] = pack2f(f1.z, f1.w);
        }

        // mid lattice
        {
            const float S = 15.f / 31.f;
            float cx = s.x * S, cy = s.y * S, cz = s.z * S;
            float flx = floorf(cx), fly = floorf(cy), flz = floorf(cz);
            int ox = min(max((int)flx - m0x, 0), 1);
            int oy = min(max((int)fly - m0y, 0), 1);
            int izm = (int)flz - 1;
            float wx[4], wy[4], wz[4];
            cubw(cx - flx, wx); cubw(cy - fly, wy); cubw(cz - flz, wz);
            accum_tile<6, 16, 0>(tile, ox, oy, izm, wx, wy, wz, tq, acc);
        }
        // coarse lattice
        {
            const float S = 7.f / 31.f;
            float cx = s.x * S, cy = s.y * S, cz = s.z * S;
            float flx = floorf(cx), fly = floorf(cy), flz = floorf(cz);
            int ox = min(max((int)flx - c0x, 0), 1);
            int oy = min(max((int)fly - c0y, 0), 1);
            int izm = (int)flz - 1;
            float wx[4], wy[4], wz[4];
            cubw(cx - flx, wx); cubw(cy - fly, wy); cubw(cz - flz, wz);
            accum_tile<6, 8, 576>(tile, ox, oy, izm, wx, wy, wz, tq, acc);
        }

        if (active) {
            int orig = __float_as_int(s.w);
            ulonglong2 oA; oA.x = acc[0]; oA.y = acc[1];   // t = 2tq
            ulonglong2 oB; oB.x = acc[2]; oB.y = acc[3];   // t = 2tq+1
            out[(size_t)(2 * tq)     * P + orig] = oA;
            out[(size_t)(2 * tq + 1) * P + orig] = oB;
        }
    }
}

// ---------------------------------------------------------------------------
extern "C" void kernel_launch(void* const* d_in, const int* in_sizes, int n_in,
                              void* d_out, int out_size) {
    // metadata order: 0:t 1:coords 2:static_0 3:coeffs_0 4:static_1 5:coeffs_1
    //                 6:static_2 7:coeffs_2
    const float* t_in   = (const float*)d_in[0];
    const float* coords = (const float*)d_in[1];
    const float* st0 = (const float*)d_in[2];
    const float* cf0 = (const float*)d_in[3];
    const float* st1 = (const float*)d_in[4];
    const float* cf1 = (const float*)d_in[5];
    const float* st2 = (const float*)d_in[6];
    const float* cf2 = (const float*)d_in[7];
    int P = in_sizes[1] / 3;
    if (P > MAXP) P = MAXP;

    cudaFuncSetAttribute(k5_main, cudaFuncAttributeMaxDynamicSharedMemorySize, SMEM2_BYTES);

    k1_hist_basis<<<(P + 255) / 256, 256>>>(t_in, coords, P);                       // 1
    k2_scan<<<1, 1024>>>();                                                         // 2
    k3_scatter_pre<<<PRE_BLOCKS + (P + 255) / 256, 256>>>(st0, cf0, st1, cf1,
                                                          st2, cf2, coords, P);     // 3
    k4_fine_gemm<<<NCOL, 256>>>(P);                                                 // 4 (profiled)
    k5_main<<<NCOL + ZERO_BLOCKS, 512, SMEM2_BYTES>>>((ulonglong2*)d_out, P);       // 5
}